// round 1
// baseline (speedup 1.0000x reference)
#include <cuda_runtime.h>
#include <cuda_bf16.h>
#include <cstdint>

// Problem constants
#define NV     100000
#define DIN    512
#define DOUT   512
#define NC     4096
#define KPC    32      // vars per cluster
#define NE     16384   // edges
#define NS     16      // shared vars per edge
#define NEG_SLOPE 0.2f

// Scratch (device globals; no allocation allowed)
__device__ float g_feats[NC * DIN];   // 8 MB
__device__ float g_Q[NC * DOUT];      // 8 MB
__device__ float g_K[NC * DOUT];      // 8 MB
__device__ float g_V[NC * DOUT];      // 8 MB

// ---------------------------------------------------------------------------
// Kernel 1: per-cluster mean pooling.  grid = NC, block = 128 (one float4/thr)
// ---------------------------------------------------------------------------
__global__ __launch_bounds__(128) void pool_kernel(
    const float* __restrict__ x, const int* __restrict__ ids)
{
    const int c = blockIdx.x;
    const int t = threadIdx.x;           // float4 column index 0..127
    __shared__ int s_ids[KPC];
    if (t < KPC) s_ids[t] = ids[c * KPC + t];
    __syncthreads();

    float4 acc = make_float4(0.f, 0.f, 0.f, 0.f);
#pragma unroll 4
    for (int k = 0; k < KPC; k++) {
        const float4 v = reinterpret_cast<const float4*>(
            x + (size_t)s_ids[k] * DIN)[t];
        acc.x += v.x; acc.y += v.y; acc.z += v.z; acc.w += v.w;
    }
    const float inv = 1.0f / (float)KPC;
    acc.x *= inv; acc.y *= inv; acc.z *= inv; acc.w *= inv;
    reinterpret_cast<float4*>(g_feats + (size_t)c * DIN)[t] = acc;
}

// ---------------------------------------------------------------------------
// Kernel 2: NT GEMM  C[m,n] = sum_k A[m,k] * B[n,k]
// A = g_feats [4096 x 512], B = W [512 x 512] (row-major, K contiguous)
// blockIdx.z in {0,1,2} selects (W_Q->g_Q, W_K->g_K, W_V->g_V)
// 128x128x8 tiling, 256 threads, 8x8 micro-tile.
// ---------------------------------------------------------------------------
#define BM 128
#define BN 128
#define BK 8
#define SPAD 132   // padded smem row length (conflict-free transposed stores)

__global__ __launch_bounds__(256) void gemm3_kernel(
    const float* __restrict__ WQ, const float* __restrict__ WK,
    const float* __restrict__ WV)
{
    const float* B;
    float* C;
    if      (blockIdx.z == 0) { B = WQ; C = g_Q; }
    else if (blockIdx.z == 1) { B = WK; C = g_K; }
    else                      { B = WV; C = g_V; }
    const float* A = g_feats;

    __shared__ float As[BK][SPAD];
    __shared__ float Bs[BK][SPAD];

    const int tid = threadIdx.x;
    const int bm  = blockIdx.y * BM;
    const int bn  = blockIdx.x * BN;

    // loader mapping: each thread loads one float4 of A and one of B per tile
    const int lr = tid >> 1;          // row within tile (0..127)
    const int lk = (tid & 1) * 4;     // k quad offset (0 or 4)

    // compute mapping: 16x16 threads, 8x8 outputs each
    const int tm8 = (tid >> 4) * 8;
    const int tn8 = (tid & 15) * 8;

    float acc[8][8];
#pragma unroll
    for (int i = 0; i < 8; i++)
#pragma unroll
        for (int j = 0; j < 8; j++) acc[i][j] = 0.f;

    for (int k0 = 0; k0 < DIN; k0 += BK) {
        // load + transpose A tile
        {
            const float4 a = *reinterpret_cast<const float4*>(
                A + (size_t)(bm + lr) * DIN + k0 + lk);
            As[lk + 0][lr] = a.x;
            As[lk + 1][lr] = a.y;
            As[lk + 2][lr] = a.z;
            As[lk + 3][lr] = a.w;
            const float4 b = *reinterpret_cast<const float4*>(
                B + (size_t)(bn + lr) * DIN + k0 + lk);
            Bs[lk + 0][lr] = b.x;
            Bs[lk + 1][lr] = b.y;
            Bs[lk + 2][lr] = b.z;
            Bs[lk + 3][lr] = b.w;
        }
        __syncthreads();

#pragma unroll
        for (int k = 0; k < BK; k++) {
            float ar[8], br[8];
            *reinterpret_cast<float4*>(ar)     = *reinterpret_cast<const float4*>(&As[k][tm8]);
            *reinterpret_cast<float4*>(ar + 4) = *reinterpret_cast<const float4*>(&As[k][tm8 + 4]);
            *reinterpret_cast<float4*>(br)     = *reinterpret_cast<const float4*>(&Bs[k][tn8]);
            *reinterpret_cast<float4*>(br + 4) = *reinterpret_cast<const float4*>(&Bs[k][tn8 + 4]);
#pragma unroll
            for (int i = 0; i < 8; i++)
#pragma unroll
                for (int j = 0; j < 8; j++)
                    acc[i][j] += ar[i] * br[j];
        }
        __syncthreads();
    }

#pragma unroll
    for (int i = 0; i < 8; i++) {
        float* crow = C + (size_t)(bm + tm8 + i) * DOUT + bn + tn8;
        *reinterpret_cast<float4*>(crow)     = *reinterpret_cast<float4*>(&acc[i][0]);
        *reinterpret_cast<float4*>(crow + 4) = *reinterpret_cast<float4*>(&acc[i][4]);
    }
}

// ---------------------------------------------------------------------------
// Kernel 3: fused edge attention + scatter.
// grid = NE, block = 128 (one float4 column per thread).
// score = dot(Q[c1], K[c2]) / sqrt(512) -> leaky_relu -> sigmoid * hw_mean
// x_out[shared_vars[e][s]] += attn * V[c2]   (vector reductions)
// ---------------------------------------------------------------------------
__device__ __forceinline__ void red_add_v4(float* addr, float4 v)
{
    asm volatile("red.global.add.v4.f32 [%0], {%1,%2,%3,%4};"
                 :: "l"(addr), "f"(v.x), "f"(v.y), "f"(v.z), "f"(v.w)
                 : "memory");
}

__global__ __launch_bounds__(128) void edge_kernel(
    const int* __restrict__ edge_index,     // [2, NE]
    const int* __restrict__ shared_vars,    // [NE, NS]
    const float* __restrict__ head_weights, // [H]
    const int* __restrict__ active_heads,   // [1]
    float* __restrict__ x_out)
{
    const int e = blockIdx.x;
    const int t = threadIdx.x;

    const int c1 = edge_index[e];
    const int c2 = edge_index[NE + e];

    const float4 q = reinterpret_cast<const float4*>(g_Q + (size_t)c1 * DOUT)[t];
    const float4 k = reinterpret_cast<const float4*>(g_K + (size_t)c2 * DOUT)[t];
    float p = q.x * k.x + q.y * k.y + q.z * k.z + q.w * k.w;

    // block reduce (4 warps)
#pragma unroll
    for (int off = 16; off > 0; off >>= 1)
        p += __shfl_xor_sync(0xFFFFFFFFu, p, off);

    __shared__ float warp_sum[4];
    __shared__ float s_attn;
    if ((t & 31) == 0) warp_sum[t >> 5] = p;
    __syncthreads();
    if (t == 0) {
        float s = warp_sum[0] + warp_sum[1] + warp_sum[2] + warp_sum[3];
        s *= rsqrtf((float)DOUT);
        s = (s >= 0.f) ? s : NEG_SLOPE * s;          // leaky relu
        const float sig = 1.0f / (1.0f + __expf(-s)); // sigmoid
        const int ah = active_heads[0];
        float hm = 0.f;
        for (int i = 0; i < ah; i++) hm += head_weights[i];
        hm /= (float)ah;
        s_attn = sig * hm;
    }

    __shared__ int s_vars[NS];
    if (t < NS) s_vars[t] = shared_vars[e * NS + t];
    __syncthreads();

    const float a = s_attn;
    float4 v = reinterpret_cast<const float4*>(g_V + (size_t)c2 * DOUT)[t];
    v.x *= a; v.y *= a; v.z *= a; v.w *= a;

#pragma unroll
    for (int s = 0; s < NS; s++) {
        float* dst = x_out + (size_t)s_vars[s] * DOUT + t * 4;
        red_add_v4(dst, v);
    }
}

// ---------------------------------------------------------------------------
// Launch
// Inputs: 0 x_var[N,512] f32, 1 W_Q[512,512], 2 W_K, 3 W_V,
//         4 head_weights[4], 5 cluster_var_ids[C,32] i32,
//         6 cluster_edge_index[2,E] i32, 7 shared_vars[E,16] i32,
//         8 active_heads i32
// Output: x_out[N,512] f32
// ---------------------------------------------------------------------------
extern "C" void kernel_launch(void* const* d_in, const int* in_sizes, int n_in,
                              void* d_out, int out_size)
{
    const float* x_var        = (const float*)d_in[0];
    const float* W_Q          = (const float*)d_in[1];
    const float* W_K          = (const float*)d_in[2];
    const float* W_V          = (const float*)d_in[3];
    const float* head_weights = (const float*)d_in[4];
    const int*   cluster_ids  = (const int*)d_in[5];
    const int*   edge_index   = (const int*)d_in[6];
    const int*   shared_vars  = (const int*)d_in[7];
    const int*   active_heads = (const int*)d_in[8];
    float*       x_out        = (float*)d_out;

    // init output = x_var
    cudaMemcpyAsync(x_out, x_var, (size_t)NV * DIN * sizeof(float),
                    cudaMemcpyDeviceToDevice);

    // cluster mean pooling
    pool_kernel<<<NC, 128>>>(x_var, cluster_ids);

    // Q/K/V projections
    dim3 ggrid(DOUT / BN, NC / BM, 3);
    gemm3_kernel<<<ggrid, 256>>>(W_Q, W_K, W_V);

    // edge attention + scatter
    edge_kernel<<<NE, 128>>>(edge_index, shared_vars, head_weights,
                             active_heads, x_out);
}

// round 2
// speedup vs baseline: 1.2209x; 1.2209x over previous
#include <cuda_runtime.h>
#include <cuda_bf16.h>
#include <cstdint>

// Problem constants
#define NV     100000
#define DIN    512
#define DOUT   512
#define NC     4096
#define KPC    32      // vars per cluster
#define NE     16384   // edges
#define NS     16      // shared vars per edge
#define NEG_SLOPE 0.2f
#define CAP    64      // max edge contributions tracked per variable

// Scratch (device globals; no allocation allowed)
__device__ float g_feats[NC * DIN];     // 8 MB
__device__ float g_Q[NC * DOUT];        // 8 MB
__device__ float g_K[NC * DOUT];        // 8 MB
__device__ float g_V[NC * DOUT];        // 8 MB
__device__ float g_attn[NE];            // 64 KB
__device__ int   g_count[NV];           // 400 KB
__device__ int   g_list[(size_t)NV * CAP]; // 25.6 MB: edge ids per variable

// ---------------------------------------------------------------------------
// Kernel 0: zero the per-var counters
// ---------------------------------------------------------------------------
__global__ void zero_count_kernel()
{
    int i = blockIdx.x * blockDim.x + threadIdx.x;
    if (i < NV) g_count[i] = 0;
}

// ---------------------------------------------------------------------------
// Kernel 1: per-cluster mean pooling.  grid = NC, block = 128 (one float4/thr)
// ---------------------------------------------------------------------------
__global__ __launch_bounds__(128) void pool_kernel(
    const float* __restrict__ x, const int* __restrict__ ids)
{
    const int c = blockIdx.x;
    const int t = threadIdx.x;           // float4 column index 0..127
    __shared__ int s_ids[KPC];
    if (t < KPC) s_ids[t] = ids[c * KPC + t];
    __syncthreads();

    float4 acc = make_float4(0.f, 0.f, 0.f, 0.f);
#pragma unroll 4
    for (int k = 0; k < KPC; k++) {
        const float4 v = reinterpret_cast<const float4*>(
            x + (size_t)s_ids[k] * DIN)[t];
        acc.x += v.x; acc.y += v.y; acc.z += v.z; acc.w += v.w;
    }
    const float inv = 1.0f / (float)KPC;
    acc.x *= inv; acc.y *= inv; acc.z *= inv; acc.w *= inv;
    reinterpret_cast<float4*>(g_feats + (size_t)c * DIN)[t] = acc;
}

// ---------------------------------------------------------------------------
// Kernel 2: NT GEMM  C[m,n] = sum_k A[m,k] * B[n,k]
// 128x128x8 tiling, 256 threads, 8x8 micro-tile.  blockIdx.z selects Q/K/V.
// ---------------------------------------------------------------------------
#define BM 128
#define BN 128
#define BK 8
#define SPAD 132   // padded smem row (conflict-free transposed stores)

__global__ __launch_bounds__(256) void gemm3_kernel(
    const float* __restrict__ WQ, const float* __restrict__ WK,
    const float* __restrict__ WV)
{
    const float* B;
    float* C;
    if      (blockIdx.z == 0) { B = WQ; C = g_Q; }
    else if (blockIdx.z == 1) { B = WK; C = g_K; }
    else                      { B = WV; C = g_V; }
    const float* A = g_feats;

    __shared__ float As[BK][SPAD];
    __shared__ float Bs[BK][SPAD];

    const int tid = threadIdx.x;
    const int bm  = blockIdx.y * BM;
    const int bn  = blockIdx.x * BN;

    const int lr = tid >> 1;          // loader row within tile (0..127)
    const int lk = (tid & 1) * 4;     // k quad offset (0 or 4)

    const int tm8 = (tid >> 4) * 8;
    const int tn8 = (tid & 15) * 8;

    float acc[8][8];
#pragma unroll
    for (int i = 0; i < 8; i++)
#pragma unroll
        for (int j = 0; j < 8; j++) acc[i][j] = 0.f;

    for (int k0 = 0; k0 < DIN; k0 += BK) {
        {
            const float4 a = *reinterpret_cast<const float4*>(
                A + (size_t)(bm + lr) * DIN + k0 + lk);
            As[lk + 0][lr] = a.x;
            As[lk + 1][lr] = a.y;
            As[lk + 2][lr] = a.z;
            As[lk + 3][lr] = a.w;
            const float4 b = *reinterpret_cast<const float4*>(
                B + (size_t)(bn + lr) * DIN + k0 + lk);
            Bs[lk + 0][lr] = b.x;
            Bs[lk + 1][lr] = b.y;
            Bs[lk + 2][lr] = b.z;
            Bs[lk + 3][lr] = b.w;
        }
        __syncthreads();

#pragma unroll
        for (int k = 0; k < BK; k++) {
            float ar[8], br[8];
            *reinterpret_cast<float4*>(ar)     = *reinterpret_cast<const float4*>(&As[k][tm8]);
            *reinterpret_cast<float4*>(ar + 4) = *reinterpret_cast<const float4*>(&As[k][tm8 + 4]);
            *reinterpret_cast<float4*>(br)     = *reinterpret_cast<const float4*>(&Bs[k][tn8]);
            *reinterpret_cast<float4*>(br + 4) = *reinterpret_cast<const float4*>(&Bs[k][tn8 + 4]);
#pragma unroll
            for (int i = 0; i < 8; i++)
#pragma unroll
                for (int j = 0; j < 8; j++)
                    acc[i][j] += ar[i] * br[j];
        }
        __syncthreads();
    }

#pragma unroll
    for (int i = 0; i < 8; i++) {
        float* crow = C + (size_t)(bm + tm8 + i) * DOUT + bn + tn8;
        *reinterpret_cast<float4*>(crow)     = *reinterpret_cast<float4*>(&acc[i][0]);
        *reinterpret_cast<float4*>(crow + 4) = *reinterpret_cast<float4*>(&acc[i][4]);
    }
}

// ---------------------------------------------------------------------------
// Kernel 3: per-edge attention score -> g_attn.  One warp per edge.
// ---------------------------------------------------------------------------
__global__ __launch_bounds__(256) void attn_kernel(
    const int* __restrict__ edge_index,
    const float* __restrict__ head_weights,
    const int* __restrict__ active_heads)
{
    const int e = (blockIdx.x * blockDim.x + threadIdx.x) >> 5;
    if (e >= NE) return;
    const int lane = threadIdx.x & 31;

    const int c1 = edge_index[e];
    const int c2 = edge_index[NE + e];
    const float4* Q4 = reinterpret_cast<const float4*>(g_Q + (size_t)c1 * DOUT);
    const float4* K4 = reinterpret_cast<const float4*>(g_K + (size_t)c2 * DOUT);

    float p = 0.f;
#pragma unroll
    for (int j = 0; j < 4; j++) {
        const float4 q = Q4[lane + 32 * j];
        const float4 k = K4[lane + 32 * j];
        p += q.x * k.x + q.y * k.y + q.z * k.z + q.w * k.w;
    }
#pragma unroll
    for (int off = 16; off > 0; off >>= 1)
        p += __shfl_xor_sync(0xFFFFFFFFu, p, off);

    if (lane == 0) {
        float s = p * rsqrtf((float)DOUT);
        s = (s >= 0.f) ? s : NEG_SLOPE * s;             // leaky relu
        const float sig = 1.0f / (1.0f + __expf(-s));   // sigmoid
        const int ah = active_heads[0];
        float hm = 0.f;
        for (int i = 0; i < ah; i++) hm += head_weights[i];
        hm /= (float)ah;
        g_attn[e] = sig * hm;
    }
}

// ---------------------------------------------------------------------------
// Kernel 4: build var -> edge incidence lists (atomic fill, bounded capacity)
// ---------------------------------------------------------------------------
__global__ void build_list_kernel(const int* __restrict__ shared_vars)
{
    const int idx = blockIdx.x * blockDim.x + threadIdx.x;  // 0..E*S-1
    if (idx >= NE * NS) return;
    const int v = shared_vars[idx];
    const int e = idx >> 4;          // NS = 16
    const int pos = atomicAdd(&g_count[v], 1);
    if (pos < CAP) g_list[(size_t)v * CAP + pos] = e;
}

// ---------------------------------------------------------------------------
// Kernel 5: gather.  x_out[v] = x_var[v] + sum_e attn[e] * V[c2[e]]
// grid = NV, block = 128 (one float4 column per thread).
// ---------------------------------------------------------------------------
__global__ __launch_bounds__(128) void gather_kernel(
    const float* __restrict__ x,
    const int* __restrict__ edge_index,
    float* __restrict__ x_out)
{
    const int v = blockIdx.x;
    const int t = threadIdx.x;

    int cnt = g_count[v];
    if (cnt > CAP) cnt = CAP;

    __shared__ float s_a[CAP];
    __shared__ int   s_c[CAP];
    if (t < cnt) {
        const int e = g_list[(size_t)v * CAP + t];
        s_a[t] = g_attn[e];
        s_c[t] = edge_index[NE + e];   // target cluster c2
    }
    __syncthreads();

    float4 acc = reinterpret_cast<const float4*>(x + (size_t)v * DIN)[t];
    for (int i = 0; i < cnt; i++) {
        const float a = s_a[i];
        const float4 w = reinterpret_cast<const float4*>(
            g_V + (size_t)s_c[i] * DOUT)[t];
        acc.x += a * w.x; acc.y += a * w.y;
        acc.z += a * w.z; acc.w += a * w.w;
    }
    reinterpret_cast<float4*>(x_out + (size_t)v * DIN)[t] = acc;
}

// ---------------------------------------------------------------------------
// Launch
// ---------------------------------------------------------------------------
extern "C" void kernel_launch(void* const* d_in, const int* in_sizes, int n_in,
                              void* d_out, int out_size)
{
    const float* x_var        = (const float*)d_in[0];
    const float* W_Q          = (const float*)d_in[1];
    const float* W_K          = (const float*)d_in[2];
    const float* W_V          = (const float*)d_in[3];
    const float* head_weights = (const float*)d_in[4];
    const int*   cluster_ids  = (const int*)d_in[5];
    const int*   edge_index   = (const int*)d_in[6];
    const int*   shared_vars  = (const int*)d_in[7];
    const int*   active_heads = (const int*)d_in[8];
    float*       x_out        = (float*)d_out;

    // reset per-var counters
    zero_count_kernel<<<(NV + 1023) / 1024, 1024>>>();

    // build var->edge incidence lists (independent of pooling/gemm)
    build_list_kernel<<<(NE * NS + 255) / 256, 256>>>(shared_vars);

    // cluster mean pooling
    pool_kernel<<<NC, 128>>>(x_var, cluster_ids);

    // Q/K/V projections
    dim3 ggrid(DOUT / BN, NC / BM, 3);
    gemm3_kernel<<<ggrid, 256>>>(W_Q, W_K, W_V);

    // per-edge attention scalars
    attn_kernel<<<(NE * 32 + 255) / 256, 256>>>(edge_index, head_weights,
                                                active_heads);

    // fused copy + gather-accumulate
    gather_kernel<<<NV, 128>>>(x_var, edge_index, x_out);
}

// round 4
// speedup vs baseline: 1.9928x; 1.6322x over previous
#include <cuda_runtime.h>
#include <cuda_bf16.h>
#include <cstdint>

// Problem constants
#define NV     100000
#define DIN    512
#define DOUT   512
#define NC     4096
#define KPC    32      // vars per cluster
#define NE     16384   // edges
#define NS     16      // shared vars per edge
#define NEG_SLOPE 0.2f
#define CAP    64      // max edge contributions tracked per variable

// Scratch (device globals; no allocation allowed)
__device__ float g_feats[NC * DIN];     // 8 MB
__device__ float g_Q[NC * DOUT];        // 8 MB
__device__ float g_K[NC * DOUT];        // 8 MB
__device__ float g_V[NC * DOUT];        // 8 MB
__device__ float g_attn[NE];            // 64 KB
__device__ int   g_count[NV];           // 400 KB
__device__ int   g_list[(size_t)NV * CAP]; // 25.6 MB

// ===========================================================================
// Kernel 0: zero counters
// ===========================================================================
__global__ void zero_count_kernel()
{
    int i = blockIdx.x * blockDim.x + threadIdx.x;
    if (i < NV) g_count[i] = 0;
}

// ===========================================================================
// Kernel 1: per-cluster mean pooling (already at DRAM roofline: 71.7%)
// ===========================================================================
__global__ __launch_bounds__(128) void pool_kernel(
    const float* __restrict__ x, const int* __restrict__ ids)
{
    const int c = blockIdx.x;
    const int t = threadIdx.x;
    __shared__ int s_ids[KPC];
    if (t < KPC) s_ids[t] = ids[c * KPC + t];
    __syncthreads();

    float4 acc = make_float4(0.f, 0.f, 0.f, 0.f);
#pragma unroll 4
    for (int k = 0; k < KPC; k++) {
        const float4 v = reinterpret_cast<const float4*>(
            x + (size_t)s_ids[k] * DIN)[t];
        acc.x += v.x; acc.y += v.y; acc.z += v.z; acc.w += v.w;
    }
    const float inv = 1.0f / (float)KPC;
    acc.x *= inv; acc.y *= inv; acc.z *= inv; acc.w *= inv;
    reinterpret_cast<float4*>(g_feats + (size_t)c * DIN)[t] = acc;
}

// ===========================================================================
// Kernel 2: tf32 tensor-core GEMM via mma.sync (sm_80+ baseline PTX).
// C[m,n] = sum_k A[m,k] * B[n,k];  A = g_feats [4096,512], B = W [512,512]
// CTA tile 128x128x32, 256 thr = 8 warps (2m x 4n), warp tile 64x32.
// Smem stride 36 floats -> conflict-free tf32 fragment loads (bank = 4r+c).
// blockIdx.z selects Q/K/V.
// ===========================================================================
#define BM 128
#define BN 128
#define BK 32
#define SSTRIDE 36

__device__ __forceinline__ uint32_t f32_to_tf32(float f)
{
    uint32_t u;
    asm("cvt.rna.tf32.f32 %0, %1;" : "=r"(u) : "f"(f));
    return u;
}

__device__ __forceinline__ void mma_tf32(
    float& d0, float& d1, float& d2, float& d3,
    uint32_t a0, uint32_t a1, uint32_t a2, uint32_t a3,
    uint32_t b0, uint32_t b1)
{
    asm volatile(
        "mma.sync.aligned.m16n8k8.row.col.f32.tf32.tf32.f32 "
        "{%0,%1,%2,%3}, {%4,%5,%6,%7}, {%8,%9}, {%0,%1,%2,%3};"
        : "+f"(d0), "+f"(d1), "+f"(d2), "+f"(d3)
        : "r"(a0), "r"(a1), "r"(a2), "r"(a3), "r"(b0), "r"(b1));
}

__global__ __launch_bounds__(256) void gemm_tc_kernel(
    const float* __restrict__ WQ, const float* __restrict__ WK,
    const float* __restrict__ WV)
{
    __shared__ uint32_t As[BM * SSTRIDE];
    __shared__ uint32_t Bs[BN * SSTRIDE];

    const float* Bsrc;
    float* C;
    if      (blockIdx.z == 0) { Bsrc = WQ; C = g_Q; }
    else if (blockIdx.z == 1) { Bsrc = WK; C = g_K; }
    else                      { Bsrc = WV; C = g_V; }
    const float* A = g_feats;

    const int tid  = threadIdx.x;
    const int wid  = tid >> 5;
    const int lane = tid & 31;
    const int bm = blockIdx.y * BM;
    const int bn = blockIdx.x * BN;

    const int warp_m = (wid >> 2) * 64;   // 0 or 64
    const int warp_n = (wid & 3) * 32;    // 0,32,64,96

    const int lr = lane >> 2;             // 0..7
    const int lc = lane & 3;              // 0..3

    float acc[4][4][4];
#pragma unroll
    for (int i = 0; i < 4; i++)
#pragma unroll
        for (int j = 0; j < 4; j++)
#pragma unroll
            for (int r = 0; r < 4; r++) acc[i][j][r] = 0.f;

    for (int k0 = 0; k0 < DIN; k0 += BK) {
        // ---- stage global -> smem (fp32 -> tf32 rounding at store) ----
#pragma unroll
        for (int i = 0; i < 4; i++) {
            const int q   = tid + i * 256;     // 0..1023 float4 slots
            const int row = q >> 3;            // 0..127
            const int kq  = (q & 7) * 4;       // 0..28
            const float4 a = *reinterpret_cast<const float4*>(
                A + (size_t)(bm + row) * DIN + k0 + kq);
            uint4 ua;
            ua.x = f32_to_tf32(a.x); ua.y = f32_to_tf32(a.y);
            ua.z = f32_to_tf32(a.z); ua.w = f32_to_tf32(a.w);
            *reinterpret_cast<uint4*>(&As[row * SSTRIDE + kq]) = ua;
            const float4 b = *reinterpret_cast<const float4*>(
                Bsrc + (size_t)(bn + row) * DIN + k0 + kq);
            uint4 ub;
            ub.x = f32_to_tf32(b.x); ub.y = f32_to_tf32(b.y);
            ub.z = f32_to_tf32(b.z); ub.w = f32_to_tf32(b.w);
            *reinterpret_cast<uint4*>(&Bs[row * SSTRIDE + kq]) = ub;
        }
        __syncthreads();

        // ---- compute 4 k8-steps ----
#pragma unroll
        for (int ks = 0; ks < 4; ks++) {
            const int kk = ks * 8;
            uint32_t af[4][4];
#pragma unroll
            for (int mf = 0; mf < 4; mf++) {
                const int rbase = (warp_m + mf * 16 + lr) * SSTRIDE + kk + lc;
                af[mf][0] = As[rbase];
                af[mf][1] = As[rbase + 8 * SSTRIDE];
                af[mf][2] = As[rbase + 4];
                af[mf][3] = As[rbase + 8 * SSTRIDE + 4];
            }
            uint32_t bf[4][2];
#pragma unroll
            for (int nf = 0; nf < 4; nf++) {
                const int rbase = (warp_n + nf * 8 + lr) * SSTRIDE + kk + lc;
                bf[nf][0] = Bs[rbase];
                bf[nf][1] = Bs[rbase + 4];
            }
#pragma unroll
            for (int mf = 0; mf < 4; mf++)
#pragma unroll
                for (int nf = 0; nf < 4; nf++)
                    mma_tf32(acc[mf][nf][0], acc[mf][nf][1],
                             acc[mf][nf][2], acc[mf][nf][3],
                             af[mf][0], af[mf][1], af[mf][2], af[mf][3],
                             bf[nf][0], bf[nf][1]);
        }
        __syncthreads();
    }

    // ---- epilogue: frag (row = lr [+8], col = 2*lc [+1]) ----
#pragma unroll
    for (int mf = 0; mf < 4; mf++) {
#pragma unroll
        for (int nf = 0; nf < 4; nf++) {
            const int row = bm + warp_m + mf * 16 + lr;
            const int col = bn + warp_n + nf * 8 + lc * 2;
            float2 v0 = make_float2(acc[mf][nf][0], acc[mf][nf][1]);
            float2 v1 = make_float2(acc[mf][nf][2], acc[mf][nf][3]);
            *reinterpret_cast<float2*>(C + (size_t)row * DOUT + col) = v0;
            *reinterpret_cast<float2*>(C + (size_t)(row + 8) * DOUT + col) = v1;
        }
    }
}

// ===========================================================================
// Kernel 3: per-edge attention score -> g_attn.  One warp per edge.
// ===========================================================================
__global__ __launch_bounds__(256) void attn_kernel(
    const int* __restrict__ edge_index,
    const float* __restrict__ head_weights,
    const int* __restrict__ active_heads)
{
    const int e = (blockIdx.x * blockDim.x + threadIdx.x) >> 5;
    if (e >= NE) return;
    const int lane = threadIdx.x & 31;

    const int c1 = edge_index[e];
    const int c2 = edge_index[NE + e];
    const float4* Q4 = reinterpret_cast<const float4*>(g_Q + (size_t)c1 * DOUT);
    const float4* K4 = reinterpret_cast<const float4*>(g_K + (size_t)c2 * DOUT);

    float p = 0.f;
#pragma unroll
    for (int j = 0; j < 4; j++) {
        const float4 q = Q4[lane + 32 * j];
        const float4 k = K4[lane + 32 * j];
        p += q.x * k.x + q.y * k.y + q.z * k.z + q.w * k.w;
    }
#pragma unroll
    for (int off = 16; off > 0; off >>= 1)
        p += __shfl_xor_sync(0xFFFFFFFFu, p, off);

    if (lane == 0) {
        float s = p * rsqrtf((float)DOUT);
        s = (s >= 0.f) ? s : NEG_SLOPE * s;
        const float sig = 1.0f / (1.0f + __expf(-s));
        const int ah = active_heads[0];
        float hm = 0.f;
        for (int i = 0; i < ah; i++) hm += head_weights[i];
        hm /= (float)ah;
        g_attn[e] = sig * hm;
    }
}

// ===========================================================================
// Kernel 4: build var -> edge incidence lists
// ===========================================================================
__global__ void build_list_kernel(const int* __restrict__ shared_vars)
{
    const int idx = blockIdx.x * blockDim.x + threadIdx.x;
    if (idx >= NE * NS) return;
    const int v = shared_vars[idx];
    const int e = idx >> 4;          // NS = 16
    const int pos = atomicAdd(&g_count[v], 1);
    if (pos < CAP) g_list[(size_t)v * CAP + pos] = e;
}

// ===========================================================================
// Kernel 5: gather. x_out[v] = x_var[v] + sum attn[e] * V[c2[e]]
// ===========================================================================
__global__ __launch_bounds__(128) void gather_kernel(
    const float* __restrict__ x,
    const int* __restrict__ edge_index,
    float* __restrict__ x_out)
{
    const int v = blockIdx.x;
    const int t = threadIdx.x;

    int cnt = g_count[v];
    if (cnt > CAP) cnt = CAP;

    __shared__ float s_a[CAP];
    __shared__ int   s_c[CAP];
    if (t < cnt) {
        const int e = g_list[(size_t)v * CAP + t];
        s_a[t] = g_attn[e];
        s_c[t] = edge_index[NE + e];
    }
    __syncthreads();

    float4 acc = reinterpret_cast<const float4*>(x + (size_t)v * DIN)[t];
    for (int i = 0; i < cnt; i++) {
        const float a = s_a[i];
        const float4 w = reinterpret_cast<const float4*>(
            g_V + (size_t)s_c[i] * DOUT)[t];
        acc.x += a * w.x; acc.y += a * w.y;
        acc.z += a * w.z; acc.w += a * w.w;
    }
    reinterpret_cast<float4*>(x_out + (size_t)v * DIN)[t] = acc;
}

// ===========================================================================
// Launch
// ===========================================================================
extern "C" void kernel_launch(void* const* d_in, const int* in_sizes, int n_in,
                              void* d_out, int out_size)
{
    const float* x_var        = (const float*)d_in[0];
    const float* W_Q          = (const float*)d_in[1];
    const float* W_K          = (const float*)d_in[2];
    const float* W_V          = (const float*)d_in[3];
    const float* head_weights = (const float*)d_in[4];
    const int*   cluster_ids  = (const int*)d_in[5];
    const int*   edge_index   = (const int*)d_in[6];
    const int*   shared_vars  = (const int*)d_in[7];
    const int*   active_heads = (const int*)d_in[8];
    float*       x_out        = (float*)d_out;

    zero_count_kernel<<<(NV + 1023) / 1024, 1024>>>();
    build_list_kernel<<<(NE * NS + 255) / 256, 256>>>(shared_vars);
    pool_kernel<<<NC, 128>>>(x_var, cluster_ids);

    dim3 ggrid(DOUT / BN, NC / BM, 3);
    gemm_tc_kernel<<<ggrid, 256>>>(W_Q, W_K, W_V);

    attn_kernel<<<(NE * 32 + 255) / 256, 256>>>(edge_index, head_weights,
                                                active_heads);
    gather_kernel<<<NV, 128>>>(x_var, edge_index, x_out);
}